// round 6
// baseline (speedup 1.0000x reference)
#include <cuda_runtime.h>

#define LSEQ 512
#define BSZ 1024
#define NTAG 64
#define START_TAG 62
#define END_TAG 63

typedef unsigned long long ull;

// ---- packed f32x2 helpers (Blackwell FFMA2: only reachable via PTX) ----
__device__ __forceinline__ ull pack2(float lo, float hi) {
    ull d;
    asm("mov.b64 %0, {%1, %2};" : "=l"(d) : "f"(lo), "f"(hi));
    return d;
}
__device__ __forceinline__ void unpack2(ull v, float& lo, float& hi) {
    asm("mov.b64 {%0, %1}, %2;" : "=f"(lo), "=f"(hi) : "l"(v));
}
__device__ __forceinline__ ull fma2(ull a, ull b, ull c) {
    ull d;
    asm("fma.rn.f32x2 %0, %1, %2, %3;" : "=l"(d) : "l"(a), "l"(b), "l"(c));
    return d;
}
__device__ __forceinline__ ull add2(ull a, ull b) {
    ull d;
    asm("add.rn.f32x2 %0, %1, %2;" : "=l"(d) : "l"(a), "l"(b));
    return d;
}

// ============================================================================
// Fused CRF kernel: TWO BATCHES per 128-thread block (grid = 512).
//
// KEY CHANGE vs best-so-far (R4): warps map to SM sub-partitions by
// wid % 4, so 64-thread blocks populate only SMSP 0/1 and leave half the
// SM's schedulers + FMA pipes idle. Packing 2 batches per block (batch A =
// warps 0,1; batch B = warps 2,3) feeds all 4 SMSPs with the SAME per-warp
// code. 128 regs x 128 thr x 4 blocks = 64K regs -> 16 warps/SM, 4/SMSP.
//
// Per-batch scheme (identical to R4): thread owns output tag t, E row in
// 64 regs as 32 f32x2 pairs; linear-domain v' = (E @ v) * exp(feat), 16
// broadcast LDS.128 + 32 FFMA2 per step, ping-pong v, one __syncthreads
// per step, renorm every 4 steps (deferred: max produced at l%4==3,
// consumed as 1/hi folded into exp(feat) and c += log(hi) at next l%4==0;
// maxsh preinit 1.0 so the first consume is a no-op, pending max at exit
// carries no obligation). feats/mask prefetched 4 steps ahead.
// Realpath (gold score) fused as a per-batch tail (64 threads x 8 gathers).
// ============================================================================
__global__ void __launch_bounds__(128, 4) crf_fused_kernel(
    const float* __restrict__ feats,
    const int*   __restrict__ tags,
    const float* __restrict__ mask,
    const float* __restrict__ transition,
    float* __restrict__ out)
{
    __shared__ __align__(16) float vsh[2][2][NTAG];  // [batch][pingpong][tag]
    __shared__ float maxsh[2][2];                    // [batch][warp-in-batch]
    __shared__ float redsh[2][6];                    // per-batch reductions

    const int tid  = threadIdx.x;
    const int bb   = tid >> 6;        // batch within block (0/1)
    const int bt   = tid & 63;        // thread within batch
    const int w    = bt >> 5;         // warp within batch (0/1)
    const int lane = tid & 31;
    const int b    = blockIdx.x * 2 + bb;
    const int t    = bt;              // output tag owned by this thread

    // E2[i] = ( exp(T[t,2i]), exp(T[t,2i+1]) )  -- 64 regs
    ull E2[32];
#pragma unroll
    for (int i = 0; i < 32; ++i) {
        E2[i] = pack2(__expf(__ldg(transition + t * NTAG + 2 * i)),
                      __expf(__ldg(transition + t * NTAG + 2 * i + 1)));
    }

    // v0 = one-hot(START), c = 0
    float myv = (t == START_TAG) ? 1.0f : 0.0f;
    vsh[bb][0][t] = myv;
    if (bt < 2) maxsh[bb][bt] = 1.0f;   // first renorm-consume is a no-op
    float c = 0.0f;
    __syncthreads();

    // 4-deep prefetch ring: this thread's feat stream + uniform mask stream
    const float* fptr = feats + (size_t)b * NTAG + t;
    float fr[4], mr[4];
#pragma unroll
    for (int u = 0; u < 4; ++u) {
        fr[u] = __ldg(fptr + (size_t)u * (BSZ * NTAG));
        mr[u] = __ldg(mask + u * BSZ + b);
    }

    for (int l4 = 0; l4 < LSEQ; l4 += 4) {
#pragma unroll
        for (int u = 0; u < 4; ++u) {
            const int l = l4 + u;
            const float f = fr[u];
            const float m = mr[u];
            int ln = l + 4;
            if (ln > LSEQ - 1) ln = LSEQ - 1;
            fr[u] = __ldg(fptr + (size_t)ln * (BSZ * NTAG));
            mr[u] = __ldg(mask + ln * BSZ + b);

            // consume deferred renorm (u==0); branch-free via maxsh preinit
            float scale = 1.0f;
            if (u == 0) {
                const float hi = fmaxf(maxsh[bb][0], maxsh[bb][1]);
                scale = __fdividef(1.0f, hi);
                c += __logf(hi);
            }
            const float ef = __expf(f) * scale;   // independent of v: hidden

            // v'[t] = sum_p E[t,p] * v[p] ; 4 f32x2 chains of depth 8
            const ulonglong2* vp = (const ulonglong2*)vsh[bb][l & 1];
            ull a0 = 0ull, a1 = 0ull, a2 = 0ull, a3 = 0ull;
            ulonglong2 wr[4];
#pragma unroll
            for (int j = 0; j < 4; ++j) wr[j] = vp[j];
#pragma unroll
            for (int i = 0; i < 16; ++i) {
                const ulonglong2 cur = wr[i & 3];
                if (i < 12) wr[i & 3] = vp[i + 4];
                if (i & 1) {
                    a2 = fma2(E2[2 * i],     cur.x, a2);
                    a3 = fma2(E2[2 * i + 1], cur.y, a3);
                } else {
                    a0 = fma2(E2[2 * i],     cur.x, a0);
                    a1 = fma2(E2[2 * i + 1], cur.y, a1);
                }
            }
            const ull s2 = add2(add2(a0, a2), add2(a1, a3));
            float sl, sh;
            unpack2(s2, sl, sh);
            float vnew = (sl + sh) * ef;

            // masked step keeps old v (pending scale still applies)
            if (m == 0.0f) vnew = myv * scale;

            myv = vnew;
            vsh[bb][(l & 1) ^ 1][t] = vnew;

            if (u == 3) {   // produce next renorm factor (consumed at u==0)
                float hi = vnew;
#pragma unroll
                for (int o = 16; o > 0; o >>= 1)
                    hi = fmaxf(hi, __shfl_xor_sync(0xffffffffu, hi, o));
                if (lane == 0) maxsh[bb][w] = hi;
            }
            __syncthreads();
        }
    }

    // allpath = c + log( sum_t v[t] * exp(T[END,t]) )  (no pending obligation)
    float s = myv * __expf(__ldg(transition + END_TAG * NTAG + t));
#pragma unroll
    for (int o = 16; o > 0; o >>= 1)
        s += __shfl_xor_sync(0xffffffffu, s, o);
    if (lane == 0) redsh[bb][w] = s;

    // ---- realpath tail: 64 threads per batch split L (8 each) ----
    float rsum = 0.0f, rlen = 0.0f;
#pragma unroll
    for (int i = 0; i < 8; ++i) {
        const int l = bt + 64 * i;
        int tag  = __ldg(tags + l * BSZ + b);
        int prev = (l == 0) ? START_TAG : __ldg(tags + (l - 1) * BSZ + b);
        float m  = __ldg(mask + l * BSZ + b);
        float emit = __ldg(feats + ((size_t)l * BSZ + b) * NTAG + tag);
        float tr   = __ldg(transition + tag * NTAG + prev);
        rsum += (emit + tr) * m;
        rlen += m;
    }
#pragma unroll
    for (int o = 16; o > 0; o >>= 1) {
        rsum += __shfl_xor_sync(0xffffffffu, rsum, o);
        rlen += __shfl_xor_sync(0xffffffffu, rlen, o);
    }
    if (lane == 0) { redsh[bb][2 + w] = rsum; redsh[bb][4 + w] = rlen; }
    __syncthreads();

    if (bt == 0) {
        const float allpath = c + __logf(redsh[bb][0] + redsh[bb][1]);
        const float rs = redsh[bb][2] + redsh[bb][3];
        const int length = (int)(redsh[bb][4] + redsh[bb][5] + 0.5f);
        const int last = (length > 0) ? __ldg(tags + (length - 1) * BSZ + b)
                                      : START_TAG;
        const float real = rs + __ldg(transition + END_TAG * NTAG + last);
        out[b] = allpath - real;
    }
}

extern "C" void kernel_launch(void* const* d_in, const int* in_sizes, int n_in,
                              void* d_out, int out_size) {
    const float* feats      = (const float*)d_in[0];
    const int*   tags       = (const int*)  d_in[1];
    const float* mask       = (const float*)d_in[2];
    const float* transition = (const float*)d_in[3];
    float* out = (float*)d_out;

    crf_fused_kernel<<<BSZ / 2, 128>>>(feats, tags, mask, transition, out);
}

// round 8
// speedup vs baseline: 1.0194x; 1.0194x over previous
#include <cuda_runtime.h>

#define LSEQ 512
#define BSZ 1024
#define NTAG 64
#define START_TAG 62
#define END_TAG 63

typedef unsigned long long ull;

// ---- packed f32x2 helpers (Blackwell FFMA2: only reachable via PTX) ----
__device__ __forceinline__ ull pack2(float lo, float hi) {
    ull d;
    asm("mov.b64 %0, {%1, %2};" : "=l"(d) : "f"(lo), "f"(hi));
    return d;
}
__device__ __forceinline__ void unpack2(ull v, float& lo, float& hi) {
    asm("mov.b64 {%0, %1}, %2;" : "=f"(lo), "=f"(hi) : "l"(v));
}
__device__ __forceinline__ ull fma2(ull a, ull b, ull c) {
    ull d;
    asm("fma.rn.f32x2 %0, %1, %2, %3;" : "=l"(d) : "l"(a), "l"(b), "l"(c));
    return d;
}
__device__ __forceinline__ ull add2(ull a, ull b) {
    ull d;
    asm("add.rn.f32x2 %0, %1, %2;" : "=l"(d) : "l"(a), "l"(b));
    return d;
}

// ---- cp.async (LDGSTS): prefetch that ptxas cannot shorten ----
__device__ __forceinline__ void cp_async4(unsigned int dst_smem, const void* src) {
    asm volatile("cp.async.ca.shared.global [%0], [%1], 4;"
                 :: "r"(dst_smem), "l"(src));
}
#define CP_COMMIT() asm volatile("cp.async.commit_group;" ::: "memory")
#define CP_WAIT(N)  asm volatile("cp.async.wait_group %0;" :: "n"(N) : "memory")

// ============================================================================
// Fused CRF kernel (R4 structure + cp.async feat staging; R7 epilogue bug
// fixed: reduction slots are now disjoint 0-1 / 2-3 / 4-5 as in R4).
//
// One batch per 64-thread block (2 warps), grid = 1024 (~7 blocks/SM, one
// wave). Thread owns tag t = tid; E row in 64 regs as 32 f32x2 pairs.
// Linear-domain forward v' = (E @ v) * exp(feat); renorm every 4 steps,
// deferred (max produced at l%4==3, consumed as 1/hi at next l%4==0).
//
// feats staged through an 8-slot SMEM ring via cp.async at prefetch
// distance 7; wait_group 6 at step top guarantees the current slot is
// complete. Latency hiding is structural, not register-allocation-dependent.
// ============================================================================
__global__ void __launch_bounds__(64, 7) crf_fused_kernel(
    const float* __restrict__ feats,
    const int*   __restrict__ tags,
    const float* __restrict__ mask,
    const float* __restrict__ transition,
    float* __restrict__ out)
{
    __shared__ __align__(16) float vsh[2][NTAG];   // ping-pong v
    __shared__ __align__(16) float fbuf[8][NTAG];  // cp.async feat ring
    __shared__ float maxsh[2];
    __shared__ float redsh[6];   // [0,1]=end-score/warp [2,3]=rsum [4,5]=rlen

    const int tid  = threadIdx.x;
    const int w    = tid >> 5;
    const int lane = tid & 31;
    const int b    = blockIdx.x;
    const int t    = tid;            // output tag owned by this thread

    // E2[i] = ( exp(T[t,2i]), exp(T[t,2i+1]) )  -- 64 regs
    ull E2[32];
#pragma unroll
    for (int i = 0; i < 32; ++i) {
        E2[i] = pack2(__expf(__ldg(transition + t * NTAG + 2 * i)),
                      __expf(__ldg(transition + t * NTAG + 2 * i + 1)));
    }

    // v0 = one-hot(START), c = 0
    float myv = (t == START_TAG) ? 1.0f : 0.0f;
    vsh[0][t] = myv;
    if (tid < 2) maxsh[tid] = 1.0f;   // first renorm-consume is a no-op
    float c = 0.0f;

    // ---- feat staging: 8-slot ring, this thread's column only ----
    const float* fsrc = feats + (size_t)b * NTAG + t;
    const unsigned int fslot =
        (unsigned int)__cvta_generic_to_shared(&fbuf[0][t]);
    // prologue: stage data for steps 0..6 (7 single-load groups)
#pragma unroll
    for (int u = 0; u < 7; ++u) {
        cp_async4(fslot + u * (NTAG * 4), fsrc + (size_t)u * (BSZ * NTAG));
        CP_COMMIT();
    }

    // mask ring (8 deep, registers; warp-uniform, cheap)
    float mr[8];
#pragma unroll
    for (int u = 0; u < 8; ++u) mr[u] = __ldg(mask + u * BSZ + b);

    __syncthreads();

    for (int l8 = 0; l8 < LSEQ; l8 += 8) {
#pragma unroll
        for (int u = 0; u < 8; ++u) {
            const int l = l8 + u;

            // current step's staged feat is complete once <=6 groups pend
            CP_WAIT(6);
            const float f = fbuf[l & 7][t];
            const float m = mr[u];

            // refill mask (distance 8) and feats (distance 7; slot (l-1)&7
            // was consumed by this same thread last step)
            int lm = l + 8; if (lm > LSEQ - 1) lm = LSEQ - 1;
            mr[u] = __ldg(mask + lm * BSZ + b);
            int lf = l + 7; if (lf > LSEQ - 1) lf = LSEQ - 1;
            cp_async4(fslot + ((l + 7) & 7) * (NTAG * 4),
                      fsrc + (size_t)lf * (BSZ * NTAG));
            CP_COMMIT();

            // consume deferred renorm (every 4th step)
            float scale = 1.0f;
            if ((u & 3) == 0) {
                const float hi = fmaxf(maxsh[0], maxsh[1]);
                scale = __fdividef(1.0f, hi);
                c += __logf(hi);
            }
            const float ef = __expf(f) * scale;   // off the MV critical path

            // v'[t] = sum_p E[t,p] * v[p] ; 4 f32x2 chains of depth 8
            const ulonglong2* vp = (const ulonglong2*)vsh[l & 1];
            ull a0 = 0ull, a1 = 0ull, a2 = 0ull, a3 = 0ull;
            ulonglong2 wr[4];
#pragma unroll
            for (int j = 0; j < 4; ++j) wr[j] = vp[j];
#pragma unroll
            for (int i = 0; i < 16; ++i) {
                const ulonglong2 cur = wr[i & 3];
                if (i < 12) wr[i & 3] = vp[i + 4];
                if (i & 1) {
                    a2 = fma2(E2[2 * i],     cur.x, a2);
                    a3 = fma2(E2[2 * i + 1], cur.y, a3);
                } else {
                    a0 = fma2(E2[2 * i],     cur.x, a0);
                    a1 = fma2(E2[2 * i + 1], cur.y, a1);
                }
            }
            const ull s2 = add2(add2(a0, a2), add2(a1, a3));
            float sl, sh;
            unpack2(s2, sl, sh);
            float vnew = (sl + sh) * ef;

            // masked step keeps old v (pending scale still applies)
            if (m == 0.0f) vnew = myv * scale;

            myv = vnew;
            vsh[(l & 1) ^ 1][t] = vnew;

            if ((u & 3) == 3) {   // produce next renorm factor
                float hi = vnew;
#pragma unroll
                for (int o = 16; o > 0; o >>= 1)
                    hi = fmaxf(hi, __shfl_xor_sync(0xffffffffu, hi, o));
                if (lane == 0) maxsh[w] = hi;
            }
            __syncthreads();
        }
    }

    // allpath = c + log( sum_t v[t] * exp(T[END,t]) )  (no pending obligation)
    float s = myv * __expf(__ldg(transition + END_TAG * NTAG + t));
#pragma unroll
    for (int o = 16; o > 0; o >>= 1)
        s += __shfl_xor_sync(0xffffffffu, s, o);
    if (lane == 0) redsh[w] = s;

    // ---- realpath tail: 64 threads split L (8 each), independent gathers --
    float rsum = 0.0f, rlen = 0.0f;
#pragma unroll
    for (int i = 0; i < 8; ++i) {
        const int l = tid + 64 * i;
        int tag  = __ldg(tags + l * BSZ + b);
        int prev = (l == 0) ? START_TAG : __ldg(tags + (l - 1) * BSZ + b);
        float m  = __ldg(mask + l * BSZ + b);
        float emit = __ldg(feats + ((size_t)l * BSZ + b) * NTAG + tag);
        float tr   = __ldg(transition + tag * NTAG + prev);
        rsum += (emit + tr) * m;
        rlen += m;
    }
#pragma unroll
    for (int o = 16; o > 0; o >>= 1) {
        rsum += __shfl_xor_sync(0xffffffffu, rsum, o);
        rlen += __shfl_xor_sync(0xffffffffu, rlen, o);
    }
    if (lane == 0) { redsh[2 + w] = rsum; redsh[4 + w] = rlen; }
    __syncthreads();

    if (tid == 0) {
        const float allpath = c + __logf(redsh[0] + redsh[1]);
        const float rs = redsh[2] + redsh[3];
        const int length = (int)(redsh[4] + redsh[5] + 0.5f);
        const int last = (length > 0) ? __ldg(tags + (length - 1) * BSZ + b)
                                      : START_TAG;
        const float real = rs + __ldg(transition + END_TAG * NTAG + last);
        out[b] = allpath - real;
    }
}

extern "C" void kernel_launch(void* const* d_in, const int* in_sizes, int n_in,
                              void* d_out, int out_size) {
    const float* feats      = (const float*)d_in[0];
    const int*   tags       = (const int*)  d_in[1];
    const float* mask       = (const float*)d_in[2];
    const float* transition = (const float*)d_in[3];
    float* out = (float*)d_out;

    crf_fused_kernel<<<BSZ, 64>>>(feats, tags, mask, transition, out);
}

// round 9
// speedup vs baseline: 1.0940x; 1.0732x over previous
#include <cuda_runtime.h>

#define LSEQ 512
#define BSZ 1024
#define NTAG 64
#define START_TAG 62
#define END_TAG 63

typedef unsigned long long ull;

// ---- packed f32x2 helpers (Blackwell FFMA2: only reachable via PTX) ----
__device__ __forceinline__ ull pack2(float lo, float hi) {
    ull d;
    asm("mov.b64 %0, {%1, %2};" : "=l"(d) : "f"(lo), "f"(hi));
    return d;
}
__device__ __forceinline__ void unpack2(ull v, float& lo, float& hi) {
    asm("mov.b64 {%0, %1}, %2;" : "=f"(lo), "=f"(hi) : "l"(v));
}
__device__ __forceinline__ ull fma2(ull a, ull b, ull c) {
    ull d;
    asm("fma.rn.f32x2 %0, %1, %2, %3;" : "=l"(d) : "l"(a), "l"(b), "l"(c));
    return d;
}
__device__ __forceinline__ ull add2(ull a, ull b) {
    ull d;
    asm("add.rn.f32x2 %0, %1, %2;" : "=l"(d) : "l"(a), "l"(b));
    return d;
}

// ============================================================================
// Fused CRF kernel, SMEM-FREE / BARRIER-FREE recurrence.
//
// One WARP per batch; 128-thread blocks hold 4 independent warps (so all 4
// SMSPs are populated). v lives in registers: lane holds (v[2*lane],
// v[2*lane+1]). The all-to-all of v' = E @ v uses shfl.sync broadcasts:
//   per step: 64 shfl.b32 + 64 FFMA2 (4 indep chains of depth 16) + misc.
// No shared memory, no barriers anywhere in the mainloop -- the cross-step
// dependency is pure register dataflow (shfl lat ~26).
//
// E row pairs for this thread's two output tags: E2[p] = (E[t0,p], E[t1,p]),
// 64 x f32x2 = 128 regs (launch_bounds(128,2) allows 256).
//
// Renorm every 4 steps, deferred off the critical path: butterfly max of the
// new v is produced after step l%4==3 (every lane gets it -- no smem), and
// 1/hi is folded into the NEXT step's exp(feat); c += log(hi) then. Pending
// max at exit needs no fixup (renorm is an identity transform on allpath).
// feats: thread's tag pair is contiguous -> LDG.64, 4-deep register ring.
// Realpath (gold score) fused as a per-warp tail (lanes split L, 16 each).
// ============================================================================
__global__ void __launch_bounds__(128, 2) crf_fused_kernel(
    const float* __restrict__ feats,
    const int*   __restrict__ tags,
    const float* __restrict__ mask,
    const float* __restrict__ transition,
    float* __restrict__ out)
{
    const int lane = threadIdx.x & 31;
    const int warp = threadIdx.x >> 5;
    const int b    = blockIdx.x * 4 + warp;   // one batch per warp
    const int t0   = 2 * lane;                // output tags owned by lane
    const int t1   = t0 + 1;

    // E2[p] = ( exp(T[t0,p]), exp(T[t1,p]) )  -- 64 f32x2 pairs = 128 regs
    ull E2[NTAG];
#pragma unroll
    for (int p = 0; p < NTAG; ++p) {
        E2[p] = pack2(__expf(__ldg(transition + t0 * NTAG + p)),
                      __expf(__ldg(transition + t1 * NTAG + p)));
    }

    // v0 = one-hot(START); c = 0; first renorm-consume is a no-op (scale=1)
    float v0 = (t0 == START_TAG) ? 1.0f : 0.0f;
    float v1 = (t1 == START_TAG) ? 1.0f : 0.0f;
    float c = 0.0f;
    float maxv = 1.0f;   // pending renorm factor, consumed at next u==0

    // 4-deep prefetch ring: feat pair (LDG.64) + warp-uniform mask
    const float* fptr = feats + (size_t)b * NTAG + t0;
    float2 fr[4];
    float  mr[4];
#pragma unroll
    for (int u = 0; u < 4; ++u) {
        fr[u] = *(const float2*)(fptr + (size_t)u * (BSZ * NTAG));
        mr[u] = __ldg(mask + u * BSZ + b);
    }

    for (int l4 = 0; l4 < LSEQ; l4 += 4) {
#pragma unroll
        for (int u = 0; u < 4; ++u) {
            const int l = l4 + u;
            const float2 f = fr[u];
            const float  m = mr[u];
            int ln = l + 4;
            if (ln > LSEQ - 1) ln = LSEQ - 1;
            fr[u] = *(const float2*)(fptr + (size_t)ln * (BSZ * NTAG));
            mr[u] = __ldg(mask + ln * BSZ + b);

            // consume deferred renorm (u==0); independent of the MV below
            float scale = 1.0f;
            if (u == 0) {
                scale = __fdividef(1.0f, maxv);
                c += __logf(maxv);
            }
            const float ef0 = __expf(f.x) * scale;
            const float ef1 = __expf(f.y) * scale;

            // v'[t] = sum_p E[t,p] * v[p] via warp broadcasts.
            // lane i's (v0,v1) are inputs p = 2i, 2i+1.
            ull a0 = 0ull, a1 = 0ull, a2 = 0ull, a3 = 0ull;
#pragma unroll
            for (int i = 0; i < 32; i += 2) {
                const float bx0 = __shfl_sync(0xffffffffu, v0, i);
                const float by0 = __shfl_sync(0xffffffffu, v1, i);
                const float bx1 = __shfl_sync(0xffffffffu, v0, i + 1);
                const float by1 = __shfl_sync(0xffffffffu, v1, i + 1);
                a0 = fma2(E2[2 * i],     pack2(bx0, bx0), a0);
                a1 = fma2(E2[2 * i + 1], pack2(by0, by0), a1);
                a2 = fma2(E2[2 * i + 2], pack2(bx1, bx1), a2);
                a3 = fma2(E2[2 * i + 3], pack2(by1, by1), a3);
            }
            const ull s2 = add2(add2(a0, a1), add2(a2, a3));
            float s0, s1;
            unpack2(s2, s0, s1);
            float n0 = s0 * ef0;
            float n1 = s1 * ef1;

            // masked step keeps old v (pending scale still applies)
            if (m == 0.0f) { n0 = v0 * scale; n1 = v1 * scale; }
            v0 = n0;
            v1 = n1;

            if (u == 3) {   // produce next renorm factor; every lane gets it
                float hi = fmaxf(n0, n1);
#pragma unroll
                for (int o = 16; o > 0; o >>= 1)
                    hi = fmaxf(hi, __shfl_xor_sync(0xffffffffu, hi, o));
                maxv = hi;
            }
        }
    }

    // allpath = c + log( sum_t v[t] * exp(T[END,t]) )  (pending max: no fixup)
    float s = v0 * __expf(__ldg(transition + END_TAG * NTAG + t0))
            + v1 * __expf(__ldg(transition + END_TAG * NTAG + t1));
#pragma unroll
    for (int o = 16; o > 0; o >>= 1)
        s += __shfl_xor_sync(0xffffffffu, s, o);
    const float allpath = c + __logf(s);

    // ---- realpath tail: lanes split L (16 each), independent gathers ----
    float rsum = 0.0f, rlen = 0.0f;
#pragma unroll
    for (int i = 0; i < 16; ++i) {
        const int l = lane + 32 * i;
        int tag  = __ldg(tags + l * BSZ + b);
        int prev = (l == 0) ? START_TAG : __ldg(tags + (l - 1) * BSZ + b);
        float m  = __ldg(mask + l * BSZ + b);
        float emit = __ldg(feats + ((size_t)l * BSZ + b) * NTAG + tag);
        float tr   = __ldg(transition + tag * NTAG + prev);
        rsum += (emit + tr) * m;
        rlen += m;
    }
#pragma unroll
    for (int o = 16; o > 0; o >>= 1) {
        rsum += __shfl_xor_sync(0xffffffffu, rsum, o);
        rlen += __shfl_xor_sync(0xffffffffu, rlen, o);
    }
    if (lane == 0) {
        const int length = (int)(rlen + 0.5f);
        const int last = (length > 0) ? __ldg(tags + (length - 1) * BSZ + b)
                                      : START_TAG;
        const float real = rsum + __ldg(transition + END_TAG * NTAG + last);
        out[b] = allpath - real;
    }
}

extern "C" void kernel_launch(void* const* d_in, const int* in_sizes, int n_in,
                              void* d_out, int out_size) {
    const float* feats      = (const float*)d_in[0];
    const int*   tags       = (const int*)  d_in[1];
    const float* mask       = (const float*)d_in[2];
    const float* transition = (const float*)d_in[3];
    float* out = (float*)d_out;

    crf_fused_kernel<<<BSZ / 4, 128>>>(feats, tags, mask, transition, out);
}